// round 3
// baseline (speedup 1.0000x reference)
#include <cuda_runtime.h>
#include <cstdint>
#include <cfloat>

#define B 8
#define H 12
#define N 1024
#define D 64
#define K 256
#define NM1 1023
#define KP1 257
#define EPSF 1e-6f

// Scratch (no cudaMalloc allowed). Zero-initialized at module load; counters
// self-reset every call so graph replays are deterministic.
__device__ float g_cls[B * N];
__device__ float g_pl[B * N];
__device__ int   g_sampled[B * K];
__device__ int   g_ids[B * KP1];
__device__ int   g_cnt_cls;
__device__ int   g_cnt[B];

// ---------------------------------------------------------------------------
// Kernel 1: cls_attn per (b,n') — one warp each — then the LAST block computes
// per-batch denominators and all pseudo-logits (threadfence-reduction pattern).
// Grid is exactly 1023 blocks x 256 threads = 8184 warps = B*NM1.
// ---------------------------------------------------------------------------
__global__ void cls_pl_kernel(const float* __restrict__ attn,
                              const float* __restrict__ value) {
    int warpid = threadIdx.x >> 5;
    int lane   = threadIdx.x & 31;
    int gw = blockIdx.x * 8 + warpid;          // 0 .. 8183, exact fit
    int b  = gw / NM1;
    int np = gw % NM1;
    int row = np + 1;

    float acc = 0.0f;
#pragma unroll
    for (int h = 0; h < H; ++h) {
        const float* v = value + (((size_t)(b * H + h)) * N + row) * D;
        float a0 = v[lane];
        float a1 = v[lane + 32];
        float s = a0 * a0 + a1 * a1;
#pragma unroll
        for (int o = 16; o > 0; o >>= 1)
            s += __shfl_xor_sync(0xFFFFFFFFu, s, o);
        float a = attn[((size_t)(b * H + h)) * ((size_t)N * N) + (size_t)row];
        acc += sqrtf(s) * a;
    }
    if (lane == 0) g_cls[b * N + np] = acc;

    // ---- last-block epilogue: denom + pseudo_logits ----
    __threadfence();
    __syncthreads();
    __shared__ int lastflag;
    if (threadIdx.x == 0) {
        int t = atomicAdd(&g_cnt_cls, 1);
        lastflag = (t == (int)gridDim.x - 1);
    }
    __syncthreads();
    if (!lastflag) return;
    if (threadIdx.x == 0) g_cnt_cls = 0;       // self-reset for next replay
    __threadfence();

    __shared__ float red[256];
    __shared__ float denom_s[B];
#pragma unroll
    for (int b2 = 0; b2 < B; ++b2) {
        float local = 0.0f;
        for (int i = threadIdx.x; i < NM1; i += 256) local += g_cls[b2 * N + i];
        red[threadIdx.x] = local;
        __syncthreads();
        for (int s = 128; s > 0; s >>= 1) {
            if (threadIdx.x < s) red[threadIdx.x] += red[threadIdx.x + s];
            __syncthreads();
        }
        if (threadIdx.x == 0) denom_s[b2] = red[0] + EPSF;
        __syncthreads();
    }
    for (int i = threadIdx.x; i < B * NM1; i += 256) {
        int b2 = i / NM1, np2 = i % NM1;
        g_pl[b2 * N + np2] = logf(g_cls[b2 * N + np2] / denom_s[b2] + EPSF);
    }
}

// ---------------------------------------------------------------------------
// Kernel 2: Gumbel argmax per (b,j) — 128 threads/block — then the LAST block
// of each batch runs the bitmap dedup+compaction (warp 0) and writes the
// mask/ids float outputs. Per-batch counters self-reset.
// ---------------------------------------------------------------------------
__global__ void argmax_dedup_kernel(const float* __restrict__ gumbel_u,
                                    float* __restrict__ out, int write_extra,
                                    size_t off_mask, size_t off_ids) {
    int bj  = blockIdx.x;            // 0 .. B*K-1
    int b   = bj / K;
    int tid = threadIdx.x;

    const float* gu = gumbel_u + (size_t)bj * NM1;
    const float* pl = g_pl + b * N;

    float best = -FLT_MAX;
    int bidx = 0x7FFFFFFF;
    for (int n = tid; n < NM1; n += 128) {
        float u = gu[n];
        float g = -logf(-logf(u + EPSF) + EPSF);
        float v = pl[n] + g;
        if (v > best || (v == best && n < bidx)) { best = v; bidx = n; }
    }

    __shared__ float sv[128];
    __shared__ int   si[128];
    sv[tid] = best; si[tid] = bidx;
    __syncthreads();
#pragma unroll
    for (int s = 64; s > 0; s >>= 1) {
        if (tid < s) {
            float v2 = sv[tid + s]; int i2 = si[tid + s];
            if (v2 > sv[tid] || (v2 == sv[tid] && i2 < si[tid])) {
                sv[tid] = v2; si[tid] = i2;
            }
        }
        __syncthreads();
    }
    if (tid == 0) g_sampled[bj] = si[0] + 1;

    // ---- last-block-per-batch dedup ----
    __threadfence();
    __shared__ int lastflag;
    if (tid == 0) lastflag = (atomicAdd(&g_cnt[b], 1) == K - 1);
    __syncthreads();
    if (!lastflag) return;
    if (tid == 0) g_cnt[b] = 0;                // self-reset
    __threadfence();

    __shared__ unsigned int bits[32];
    if (tid < 32) {
        int lane = tid;
        bits[lane] = 0u;
        __syncwarp();
        for (int i = lane; i < K; i += 32) {
            int s = g_sampled[b * K + i];      // 1..1023
            atomicOr(&bits[s >> 5], 1u << (s & 31));
        }
        __syncwarp();

        unsigned int myword = bits[lane];
        int cnt = __popc(myword);
        int incl = cnt;
#pragma unroll
        for (int o = 1; o < 32; o <<= 1) {
            int t = __shfl_up_sync(0xFFFFFFFFu, incl, o);
            if (lane >= o) incl += t;
        }
        int U = __shfl_sync(0xFFFFFFFFu, incl, 31);
        int excl = incl - cnt;
        int zeros = KP1 - U;

        for (int t = lane; t < zeros; t += 32) g_ids[b * KP1 + t] = 0;

        int pos = zeros + excl;
        unsigned int m = myword;
        while (m) {
            int p = __ffs(m) - 1;
            m &= m - 1;
            g_ids[b * KP1 + pos] = lane * 32 + p;
            pos++;
        }
        __syncwarp();

        if (write_extra) {
            for (int t = lane; t < KP1; t += 32) {
                int idv = g_ids[b * KP1 + t];
                out[off_mask + (size_t)b * KP1 + t] = (t == 0 || idv != 0) ? 1.0f : 0.0f;
                out[off_ids  + (size_t)b * KP1 + t] = (float)idv;
            }
        }
    }
}

// ---------------------------------------------------------------------------
// Kernel 3: row gather. new_attn[b,h,j,:] = attn[b,h,id,:].
// Streaming stores: output is never re-read; keep L2 for duplicated src rows.
// ---------------------------------------------------------------------------
__global__ void gather_kernel(const float* __restrict__ attn,
                              float* __restrict__ out) {
    int j  = blockIdx.x;                 // 0..256
    int bh = blockIdx.y;                 // 0..95
    int b  = bh / H;
    int id = g_ids[b * KP1 + j];

    const float4* src = (const float4*)(attn + ((size_t)bh * N + id) * N);
    float4*       dst = (float4*)(out  + ((size_t)bh * KP1 + j) * N);
    float4 v = __ldg(src + threadIdx.x);
    __stcs(dst + threadIdx.x, v);
}

// ---------------------------------------------------------------------------
extern "C" void kernel_launch(void* const* d_in, const int* in_sizes, int n_in,
                              void* d_out, int out_size) {
    const float* attn     = (const float*)d_in[0];
    const float* value    = (const float*)d_in[1];
    const float* gumbel_u = (const float*)d_in[3];
    float* out = (float*)d_out;

    const size_t ATTN_OUT = (size_t)B * H * KP1 * N;     // 25,276,416
    const size_t MASK_OUT = (size_t)B * KP1;             // 2,056
    const size_t TOTAL    = ATTN_OUT + 2 * MASK_OUT;
    int write_extra = ((size_t)out_size >= TOTAL) ? 1 : 0;

    cls_pl_kernel<<<1023, 256>>>(attn, value);
    argmax_dedup_kernel<<<B * K, 128>>>(gumbel_u, out, write_extra,
                                        ATTN_OUT, ATTN_OUT + MASK_OUT);
    dim3 grid(KP1, B * H);
    gather_kernel<<<grid, 256>>>(attn, out);
}

// round 4
// speedup vs baseline: 1.2537x; 1.2537x over previous
#include <cuda_runtime.h>
#include <cstdint>
#include <cfloat>

#define B 8
#define H 12
#define N 1024
#define D 64
#define K 256
#define NM1 1023
#define KP1 257
#define EPSF 1e-6f

// Scratch (no cudaMalloc). Zero-initialized at load; counters/accumulators
// self-reset every call so graph replays are deterministic.
__device__ float g_cls[B * N];
__device__ float g_denom[B];        // raw sum (atomic), reset by pl last block
__device__ float g_pl[B * N];
__device__ int   g_sampled[B * K];
__device__ int   g_ids[B * KP1];
__device__ int   g_cnt_pl;
__device__ int   g_cnt[B];

// ---------------------------------------------------------------------------
// Kernel 1: cls_attn[b,n'] = sum_h attn[b,h,0,1+n'] * ||value[b,h,1+n',:]||
// 8 rows per warp, 4 lanes per row (each lane: 4x float4 = 16 elements).
// Also accumulates the per-batch denominator via one red.add per warp.
// Grid: B*128 warps = 1024 warps = 128 blocks x 256 threads.
// ---------------------------------------------------------------------------
__global__ void cls_kernel(const float* __restrict__ attn,
                           const float* __restrict__ value) {
    int warpid = threadIdx.x >> 5;
    int lane   = threadIdx.x & 31;
    int gw = blockIdx.x * 8 + warpid;       // 0..1023
    int b  = gw >> 7;                       // uniform within warp
    int w  = gw & 127;

    int q = lane >> 2;                      // 0..7 : row within warp
    int c = lane & 3;                       // 0..3 : chunk within row
    int np = w * 8 + q;                     // 0..1023
    bool valid = (np < NM1);
    int row = valid ? (np + 1) : 1;         // dummy row for invalid (no OOB)

    float acc = 0.0f;
#pragma unroll
    for (int h = 0; h < H; ++h) {
        const float4* v4 = (const float4*)(value + (((size_t)(b * H + h)) * N + row) * D);
        float s = 0.0f;
#pragma unroll
        for (int kk = 0; kk < 4; ++kk) {
            float4 t = v4[c + 4 * kk];
            s += t.x * t.x + t.y * t.y + t.z * t.z + t.w * t.w;
        }
        // sum over the 4 lanes of this quad
        s += __shfl_xor_sync(0xFFFFFFFFu, s, 1);
        s += __shfl_xor_sync(0xFFFFFFFFu, s, 2);
        float a = attn[((size_t)(b * H + h)) * ((size_t)N * N) + (size_t)row];
        acc += sqrtf(s) * a;
    }
    if (!valid) acc = 0.0f;
    if (valid && c == 0) g_cls[b * N + np] = acc;

    // denominator: every row value appears in 4 lanes -> warp sum * 0.25 (exact)
    float t = acc;
#pragma unroll
    for (int o = 16; o > 0; o >>= 1) t += __shfl_xor_sync(0xFFFFFFFFu, t, o);
    if (lane == 0) atomicAdd(&g_denom[b], t * 0.25f);
}

// ---------------------------------------------------------------------------
// Kernel 2: pseudo_logits (embarrassingly parallel; denom already computed).
// Last block resets g_denom for the next graph replay.
// Grid: 32 x 256.
// ---------------------------------------------------------------------------
__global__ void pl_kernel() {
    int i = blockIdx.x * 256 + threadIdx.x;   // 0..8191
    int b  = i >> 10;
    int np = i & 1023;
    float denom = g_denom[b] + EPSF;
    if (np < NM1) g_pl[b * N + np] = logf(g_cls[b * N + np] / denom + EPSF);

    __threadfence();
    __syncthreads();
    __shared__ int lastflag;
    if (threadIdx.x == 0) lastflag = (atomicAdd(&g_cnt_pl, 1) == (int)gridDim.x - 1);
    __syncthreads();
    if (lastflag) {
        if (threadIdx.x < B) g_denom[threadIdx.x] = 0.0f;
        if (threadIdx.x == 0) g_cnt_pl = 0;
    }
}

// ---------------------------------------------------------------------------
// Kernel 3: Gumbel argmax per (b,j); last block per batch runs bitmap dedup
// and writes the mask/ids float outputs.
// ---------------------------------------------------------------------------
__global__ void argmax_dedup_kernel(const float* __restrict__ gumbel_u,
                                    float* __restrict__ out, int write_extra,
                                    size_t off_mask, size_t off_ids) {
    int bj  = blockIdx.x;            // 0 .. B*K-1
    int b   = bj / K;
    int tid = threadIdx.x;

    const float* gu = gumbel_u + (size_t)bj * NM1;
    const float* pl = g_pl + b * N;

    float best = -FLT_MAX;
    int bidx = 0x7FFFFFFF;
    for (int n = tid; n < NM1; n += 128) {
        float u = gu[n];
        float g = -logf(-logf(u + EPSF) + EPSF);
        float v = pl[n] + g;
        if (v > best || (v == best && n < bidx)) { best = v; bidx = n; }
    }

    __shared__ float sv[128];
    __shared__ int   si[128];
    sv[tid] = best; si[tid] = bidx;
    __syncthreads();
#pragma unroll
    for (int s = 64; s > 0; s >>= 1) {
        if (tid < s) {
            float v2 = sv[tid + s]; int i2 = si[tid + s];
            if (v2 > sv[tid] || (v2 == sv[tid] && i2 < si[tid])) {
                sv[tid] = v2; si[tid] = i2;
            }
        }
        __syncthreads();
    }
    if (tid == 0) g_sampled[bj] = si[0] + 1;

    // ---- last-block-per-batch dedup (tiny epilogue: OK to fuse) ----
    __threadfence();
    __shared__ int lastflag;
    if (tid == 0) lastflag = (atomicAdd(&g_cnt[b], 1) == K - 1);
    __syncthreads();
    if (!lastflag) return;
    if (tid == 0) g_cnt[b] = 0;                // self-reset
    __threadfence();

    __shared__ unsigned int bits[32];
    if (tid < 32) {
        int lane = tid;
        bits[lane] = 0u;
        __syncwarp();
        for (int i = lane; i < K; i += 32) {
            int s = g_sampled[b * K + i];      // 1..1023
            atomicOr(&bits[s >> 5], 1u << (s & 31));
        }
        __syncwarp();

        unsigned int myword = bits[lane];
        int cnt = __popc(myword);
        int incl = cnt;
#pragma unroll
        for (int o = 1; o < 32; o <<= 1) {
            int t = __shfl_up_sync(0xFFFFFFFFu, incl, o);
            if (lane >= o) incl += t;
        }
        int U = __shfl_sync(0xFFFFFFFFu, incl, 31);
        int excl = incl - cnt;
        int zeros = KP1 - U;

        for (int t = lane; t < zeros; t += 32) g_ids[b * KP1 + t] = 0;

        int pos = zeros + excl;
        unsigned int m = myword;
        while (m) {
            int p = __ffs(m) - 1;
            m &= m - 1;
            g_ids[b * KP1 + pos] = lane * 32 + p;
            pos++;
        }
        __syncwarp();

        if (write_extra) {
            for (int t = lane; t < KP1; t += 32) {
                int idv = g_ids[b * KP1 + t];
                out[off_mask + (size_t)b * KP1 + t] = (t == 0 || idv != 0) ? 1.0f : 0.0f;
                out[off_ids  + (size_t)b * KP1 + t] = (float)idv;
            }
        }
    }
}

// ---------------------------------------------------------------------------
// Kernel 4: row gather. new_attn[b,h,j,:] = attn[b,h,id,:]. Streaming stores.
// ---------------------------------------------------------------------------
__global__ void gather_kernel(const float* __restrict__ attn,
                              float* __restrict__ out) {
    int j  = blockIdx.x;                 // 0..256
    int bh = blockIdx.y;                 // 0..95
    int b  = bh / H;
    int id = g_ids[b * KP1 + j];

    const float4* src = (const float4*)(attn + ((size_t)bh * N + id) * N);
    float4*       dst = (float4*)(out  + ((size_t)bh * KP1 + j) * N);
    float4 v = __ldg(src + threadIdx.x);
    __stcs(dst + threadIdx.x, v);
}

// ---------------------------------------------------------------------------
extern "C" void kernel_launch(void* const* d_in, const int* in_sizes, int n_in,
                              void* d_out, int out_size) {
    const float* attn     = (const float*)d_in[0];
    const float* value    = (const float*)d_in[1];
    const float* gumbel_u = (const float*)d_in[3];
    float* out = (float*)d_out;

    const size_t ATTN_OUT = (size_t)B * H * KP1 * N;     // 25,276,416
    const size_t MASK_OUT = (size_t)B * KP1;             // 2,056
    const size_t TOTAL    = ATTN_OUT + 2 * MASK_OUT;
    int write_extra = ((size_t)out_size >= TOTAL) ? 1 : 0;

    cls_kernel<<<128, 256>>>(attn, value);
    pl_kernel<<<32, 256>>>();
    argmax_dedup_kernel<<<B * K, 128>>>(gumbel_u, out, write_extra,
                                        ATTN_OUT, ATTN_OUT + MASK_OUT);
    dim3 grid(KP1, B * H);
    gather_kernel<<<grid, 256>>>(attn, out);
}

// round 5
// speedup vs baseline: 1.3532x; 1.0793x over previous
#include <cuda_runtime.h>
#include <cstdint>
#include <cfloat>

#define B 8
#define H 12
#define N 1024
#define D 64
#define K 256
#define NM1 1023
#define KP1 257
#define EPSF 1e-6f

// Scratch (no cudaMalloc). Zero-init at load; counters/accumulators self-reset
// every call so graph replays are deterministic.
__device__ float g_cls[B * N];
__device__ float g_denom[B];        // atomic sum; reset by per-batch dedup block
__device__ int   g_sampled[B * K];
__device__ int   g_ids[B * KP1];
__device__ int   g_cnt[B];

// ---------------------------------------------------------------------------
// Kernel 1: cls_attn[b,n'] = sum_h attn[b,h,0,1+n'] * ||value[b,h,1+n',:]||
// 8 rows/warp, 4 lanes/row (4x float4 each). One red.add per warp for denom.
// Grid: 128 x 256 (= B*128 warps).
// ---------------------------------------------------------------------------
__global__ void cls_kernel(const float* __restrict__ attn,
                           const float* __restrict__ value) {
    int warpid = threadIdx.x >> 5;
    int lane   = threadIdx.x & 31;
    int gw = blockIdx.x * 8 + warpid;       // 0..1023
    int b  = gw >> 7;
    int w  = gw & 127;

    int q = lane >> 2;                      // row within warp
    int c = lane & 3;                       // chunk within row
    int np = w * 8 + q;
    bool valid = (np < NM1);
    int row = valid ? (np + 1) : 1;

    float acc = 0.0f;
#pragma unroll
    for (int h = 0; h < H; ++h) {
        const float4* v4 = (const float4*)(value + (((size_t)(b * H + h)) * N + row) * D);
        float s = 0.0f;
#pragma unroll
        for (int kk = 0; kk < 4; ++kk) {
            float4 t = v4[c + 4 * kk];
            s += t.x * t.x + t.y * t.y + t.z * t.z + t.w * t.w;
        }
        s += __shfl_xor_sync(0xFFFFFFFFu, s, 1);
        s += __shfl_xor_sync(0xFFFFFFFFu, s, 2);
        float a = attn[((size_t)(b * H + h)) * ((size_t)N * N) + (size_t)row];
        acc += sqrtf(s) * a;
    }
    if (!valid) acc = 0.0f;
    if (valid && c == 0) g_cls[b * N + np] = acc;

    float t = acc;
#pragma unroll
    for (int o = 16; o > 0; o >>= 1) t += __shfl_xor_sync(0xFFFFFFFFu, t, o);
    if (lane == 0) atomicAdd(&g_denom[b], t * 0.25f);
}

// ---------------------------------------------------------------------------
// Kernel 2: ratio-space Gumbel argmax + per-batch dedup.
//   argmax_n( log(c/l) ) == argmax_n( c[n]/l[n] ),  c = cls/denom + eps,
//   l = -log(u+eps)+eps  (both > 0).  Compare via c*bl > bc*l (no division,
//   one logf per element). Last block of each batch: bitmap dedup, mask/ids
//   outputs, counter + denom self-reset.
// ---------------------------------------------------------------------------
__global__ void argmax_dedup_kernel(const float* __restrict__ gumbel_u,
                                    float* __restrict__ out, int write_extra,
                                    size_t off_mask, size_t off_ids) {
    int bj  = blockIdx.x;            // 0 .. B*K-1
    int b   = bj / K;
    int tid = threadIdx.x;           // 128

    const float* gu  = gumbel_u + (size_t)bj * NM1;
    const float* cls = g_cls + b * N;
    float invd = 1.0f / (g_denom[b] + EPSF);

    float bc = 0.0f, bl = 1.0f;      // ratio 0: any candidate wins (c >= eps)
    int bidx = 0x7FFFFFFF;
    for (int n = tid; n < NM1; n += 128) {
        float u = gu[n];
        float l = -logf(u + EPSF) + EPSF;
        float c = fmaf(cls[n], invd, EPSF);
        float lhs = c * bl, rhs = bc * l;
        if (lhs > rhs || (lhs == rhs && n < bidx)) { bc = c; bl = l; bidx = n; }
    }

    __shared__ float svc[128];
    __shared__ float svl[128];
    __shared__ int   si[128];
    svc[tid] = bc; svl[tid] = bl; si[tid] = bidx;
    __syncthreads();
#pragma unroll
    for (int s = 64; s > 0; s >>= 1) {
        if (tid < s) {
            float c2 = svc[tid + s], l2 = svl[tid + s]; int i2 = si[tid + s];
            float lhs = c2 * svl[tid], rhs = svc[tid] * l2;
            if (lhs > rhs || (lhs == rhs && i2 < si[tid])) {
                svc[tid] = c2; svl[tid] = l2; si[tid] = i2;
            }
        }
        __syncthreads();
    }
    if (tid == 0) g_sampled[bj] = si[0] + 1;

    // ---- last-block-per-batch dedup ----
    __threadfence();
    __shared__ int lastflag;
    if (tid == 0) lastflag = (atomicAdd(&g_cnt[b], 1) == K - 1);
    __syncthreads();
    if (!lastflag) return;
    if (tid == 0) { g_cnt[b] = 0; g_denom[b] = 0.0f; }   // self-reset
    __threadfence();

    __shared__ unsigned int bits[32];
    if (tid < 32) {
        int lane = tid;
        bits[lane] = 0u;
        __syncwarp();
        for (int i = lane; i < K; i += 32) {
            int s = g_sampled[b * K + i];      // 1..1023
            atomicOr(&bits[s >> 5], 1u << (s & 31));
        }
        __syncwarp();

        unsigned int myword = bits[lane];
        int cnt = __popc(myword);
        int incl = cnt;
#pragma unroll
        for (int o = 1; o < 32; o <<= 1) {
            int t = __shfl_up_sync(0xFFFFFFFFu, incl, o);
            if (lane >= o) incl += t;
        }
        int U = __shfl_sync(0xFFFFFFFFu, incl, 31);
        int excl = incl - cnt;
        int zeros = KP1 - U;

        for (int t = lane; t < zeros; t += 32) g_ids[b * KP1 + t] = 0;

        int pos = zeros + excl;
        unsigned int m = myword;
        while (m) {
            int p = __ffs(m) - 1;
            m &= m - 1;
            g_ids[b * KP1 + pos] = lane * 32 + p;
            pos++;
        }
        __syncwarp();

        if (write_extra) {
            for (int t = lane; t < KP1; t += 32) {
                int idv = g_ids[b * KP1 + t];
                out[off_mask + (size_t)b * KP1 + t] = (t == 0 || idv != 0) ? 1.0f : 0.0f;
                out[off_ids  + (size_t)b * KP1 + t] = (float)idv;
            }
        }
    }
}

// ---------------------------------------------------------------------------
// Kernel 3: row gather, 12-way ILP. Block = one (b, j): all H head-rows.
// Load 12 independent float4s into registers, then store 12 (streaming).
// ---------------------------------------------------------------------------
__global__ void gather_kernel(const float* __restrict__ attn,
                              float* __restrict__ out) {
    int j = blockIdx.x;                  // 0..256
    int b = blockIdx.y;                  // 0..7
    int t = threadIdx.x;                 // 0..255
    int id = g_ids[b * KP1 + j];

    float4 v[H];
#pragma unroll
    for (int h = 0; h < H; ++h) {
        const float4* src = (const float4*)(attn + (((size_t)(b * H + h)) * N + id) * N);
        v[h] = __ldg(src + t);
    }
#pragma unroll
    for (int h = 0; h < H; ++h) {
        float4* dst = (float4*)(out + (((size_t)(b * H + h)) * KP1 + j) * N);
        __stcs(dst + t, v[h]);
    }
}

// ---------------------------------------------------------------------------
extern "C" void kernel_launch(void* const* d_in, const int* in_sizes, int n_in,
                              void* d_out, int out_size) {
    const float* attn     = (const float*)d_in[0];
    const float* value    = (const float*)d_in[1];
    const float* gumbel_u = (const float*)d_in[3];
    float* out = (float*)d_out;

    const size_t ATTN_OUT = (size_t)B * H * KP1 * N;     // 25,276,416
    const size_t MASK_OUT = (size_t)B * KP1;             // 2,056
    const size_t TOTAL    = ATTN_OUT + 2 * MASK_OUT;
    int write_extra = ((size_t)out_size >= TOTAL) ? 1 : 0;

    cls_kernel<<<128, 256>>>(attn, value);
    argmax_dedup_kernel<<<B * K, 128>>>(gumbel_u, out, write_extra,
                                        ATTN_OUT, ATTN_OUT + MASK_OUT);
    dim3 grid(KP1, B);
    gather_kernel<<<grid, 256>>>(attn, out);
}

// round 6
// speedup vs baseline: 1.3698x; 1.0123x over previous
#include <cuda_runtime.h>
#include <cstdint>
#include <cfloat>

#define B 8
#define H 12
#define N 1024
#define D 64
#define K 256
#define NM1 1023
#define KP1 257
#define EPSF 1e-6f

// Scratch (no cudaMalloc). Zero-init at load; counters/accumulators self-reset
// every call so graph replays are deterministic.
__device__ float g_cls[B * N];
__device__ float g_denom[B];        // atomic sum; reset by per-batch dedup block
__device__ int   g_sampled[B * K];
__device__ int   g_ids[B * KP1];
__device__ int   g_cnt[B];

// ---------------------------------------------------------------------------
// Kernel 1: cls_attn[b,n'] = sum_h attn[b,h,0,1+n'] * ||value[b,h,1+n',:]||
// 2 rows/warp, 16 lanes/row, one float4 per lane per head. ALL 24 loads
// (12 value float4 + 12 attn scalars) front-batched for MLP, then pure math.
// Grid: 512 x 256 = 4096 warps (= B*512).
// ---------------------------------------------------------------------------
__global__ void cls_kernel(const float* __restrict__ attn,
                           const float* __restrict__ value) {
    int warpid = threadIdx.x >> 5;
    int lane   = threadIdx.x & 31;
    int gw = blockIdx.x * 8 + warpid;       // 0..4095
    int b  = gw >> 9;                       // 512 warps per batch
    int w  = gw & 511;

    int sub = lane >> 4;                    // row within warp (0/1)
    int c   = lane & 15;                    // float4 chunk within row (0..15)
    int np  = w * 2 + sub;                  // 0..1023
    bool valid = (np < NM1);
    int row = valid ? (np + 1) : 1;

    // Front-batched loads: 12 independent float4 + 12 broadcast scalars.
    float4 v[H];
    float  a[H];
#pragma unroll
    for (int h = 0; h < H; ++h) {
        const float4* v4 = (const float4*)(value + (((size_t)(b * H + h)) * N + row) * D);
        v[h] = v4[c];
        a[h] = attn[((size_t)(b * H + h)) * ((size_t)N * N) + (size_t)row];
    }

    float acc = 0.0f;
#pragma unroll
    for (int h = 0; h < H; ++h) {
        float s = v[h].x * v[h].x + v[h].y * v[h].y
                + v[h].z * v[h].z + v[h].w * v[h].w;
        // reduce across the 16 lanes of this row
        s += __shfl_xor_sync(0xFFFFFFFFu, s, 1);
        s += __shfl_xor_sync(0xFFFFFFFFu, s, 2);
        s += __shfl_xor_sync(0xFFFFFFFFu, s, 4);
        s += __shfl_xor_sync(0xFFFFFFFFu, s, 8);
        acc += sqrtf(s) * a[h];
    }
    if (!valid) acc = 0.0f;
    if (valid && c == 0) g_cls[b * N + np] = acc;

    // denominator: each row value present in 16 lanes -> warp sum * (1/16), exact
    float t = acc;
#pragma unroll
    for (int o = 16; o > 0; o >>= 1) t += __shfl_xor_sync(0xFFFFFFFFu, t, o);
    if (lane == 0) atomicAdd(&g_denom[b], t * 0.0625f);
}

// ---------------------------------------------------------------------------
// Kernel 2: ratio-space Gumbel argmax + per-batch dedup.
//   argmax_n( log(c/l) ) == argmax_n( c[n]/l[n] ),  c = cls/denom + eps,
//   l = -log(u+eps)+eps (both > 0). Compare via c*bl > bc*l.
// Last block per batch: bitmap dedup + mask/ids outputs + self-reset.
// ---------------------------------------------------------------------------
__global__ void argmax_dedup_kernel(const float* __restrict__ gumbel_u,
                                    float* __restrict__ out, int write_extra,
                                    size_t off_mask, size_t off_ids) {
    int bj  = blockIdx.x;            // 0 .. B*K-1
    int b   = bj / K;
    int tid = threadIdx.x;           // 128

    const float* gu  = gumbel_u + (size_t)bj * NM1;
    const float* cls = g_cls + b * N;
    float invd = 1.0f / (g_denom[b] + EPSF);

    float bc = 0.0f, bl = 1.0f;
    int bidx = 0x7FFFFFFF;
    for (int n = tid; n < NM1; n += 128) {
        float u = gu[n];
        float l = -logf(u + EPSF) + EPSF;
        float c = fmaf(cls[n], invd, EPSF);
        float lhs = c * bl, rhs = bc * l;
        if (lhs > rhs || (lhs == rhs && n < bidx)) { bc = c; bl = l; bidx = n; }
    }

    __shared__ float svc[128];
    __shared__ float svl[128];
    __shared__ int   si[128];
    svc[tid] = bc; svl[tid] = bl; si[tid] = bidx;
    __syncthreads();
#pragma unroll
    for (int s = 64; s > 0; s >>= 1) {
        if (tid < s) {
            float c2 = svc[tid + s], l2 = svl[tid + s]; int i2 = si[tid + s];
            float lhs = c2 * svl[tid], rhs = svc[tid] * l2;
            if (lhs > rhs || (lhs == rhs && i2 < si[tid])) {
                svc[tid] = c2; svl[tid] = l2; si[tid] = i2;
            }
        }
        __syncthreads();
    }
    if (tid == 0) g_sampled[bj] = si[0] + 1;

    // ---- last-block-per-batch dedup ----
    __threadfence();
    __shared__ int lastflag;
    if (tid == 0) lastflag = (atomicAdd(&g_cnt[b], 1) == K - 1);
    __syncthreads();
    if (!lastflag) return;
    if (tid == 0) { g_cnt[b] = 0; g_denom[b] = 0.0f; }   // self-reset
    __threadfence();

    __shared__ unsigned int bits[32];
    if (tid < 32) {
        int lane = tid;
        bits[lane] = 0u;
        __syncwarp();
        for (int i = lane; i < K; i += 32) {
            int s = g_sampled[b * K + i];      // 1..1023
            atomicOr(&bits[s >> 5], 1u << (s & 31));
        }
        __syncwarp();

        unsigned int myword = bits[lane];
        int cnt = __popc(myword);
        int incl = cnt;
#pragma unroll
        for (int o = 1; o < 32; o <<= 1) {
            int t = __shfl_up_sync(0xFFFFFFFFu, incl, o);
            if (lane >= o) incl += t;
        }
        int U = __shfl_sync(0xFFFFFFFFu, incl, 31);
        int excl = incl - cnt;
        int zeros = KP1 - U;

        for (int t = lane; t < zeros; t += 32) g_ids[b * KP1 + t] = 0;

        int pos = zeros + excl;
        unsigned int m = myword;
        while (m) {
            int p = __ffs(m) - 1;
            m &= m - 1;
            g_ids[b * KP1 + pos] = lane * 32 + p;
            pos++;
        }
        __syncwarp();

        if (write_extra) {
            for (int t = lane; t < KP1; t += 32) {
                int idv = g_ids[b * KP1 + t];
                out[off_mask + (size_t)b * KP1 + t] = (t == 0 || idv != 0) ? 1.0f : 0.0f;
                out[off_ids  + (size_t)b * KP1 + t] = (float)idv;
            }
        }
    }
}

// ---------------------------------------------------------------------------
// Kernel 3: row gather, 12-way ILP. Block = one (b, j): all H head-rows.
// Load 12 independent float4s into registers, then store 12 (streaming).
// ---------------------------------------------------------------------------
__global__ void gather_kernel(const float* __restrict__ attn,
                              float* __restrict__ out) {
    int j = blockIdx.x;                  // 0..256
    int b = blockIdx.y;                  // 0..7
    int t = threadIdx.x;                 // 0..255
    int id = g_ids[b * KP1 + j];

    float4 v[H];
#pragma unroll
    for (int h = 0; h < H; ++h) {
        const float4* src = (const float4*)(attn + (((size_t)(b * H + h)) * N + id) * N);
        v[h] = __ldg(src + t);
    }
#pragma unroll
    for (int h = 0; h < H; ++h) {
        float4* dst = (float4*)(out + (((size_t)(b * H + h)) * KP1 + j) * N);
        __stcs(dst + t, v[h]);
    }
}

// ---------------------------------------------------------------------------
extern "C" void kernel_launch(void* const* d_in, const int* in_sizes, int n_in,
                              void* d_out, int out_size) {
    const float* attn     = (const float*)d_in[0];
    const float* value    = (const float*)d_in[1];
    const float* gumbel_u = (const float*)d_in[3];
    float* out = (float*)d_out;

    const size_t ATTN_OUT = (size_t)B * H * KP1 * N;     // 25,276,416
    const size_t MASK_OUT = (size_t)B * KP1;             // 2,056
    const size_t TOTAL    = ATTN_OUT + 2 * MASK_OUT;
    int write_extra = ((size_t)out_size >= TOTAL) ? 1 : 0;

    cls_kernel<<<512, 256>>>(attn, value);
    argmax_dedup_kernel<<<B * K, 128>>>(gumbel_u, out, write_extra,
                                        ATTN_OUT, ATTN_OUT + MASK_OUT);
    dim3 grid(KP1, B);
    gather_kernel<<<grid, 256>>>(attn, out);
}

// round 7
// speedup vs baseline: 1.4026x; 1.0240x over previous
#include <cuda_runtime.h>
#include <cstdint>
#include <cfloat>

#define B 8
#define H 12
#define N 1024
#define D 64
#define K 256
#define NM1 1023
#define KP1 257
#define EPSF 1e-6f

// Scratch (no cudaMalloc). Zero-init at load; counters/accumulators self-reset
// every call so graph replays are deterministic.
__device__ float g_cls[B * N];
__device__ float g_denom[B];        // atomic sum; reset by per-batch dedup block
__device__ int   g_sampled[B * K];
__device__ int   g_ids[B * KP1];
__device__ int   g_cnt[B];

// ---------------------------------------------------------------------------
// Kernel 1: cls_attn[b,n'] = sum_h attn[b,h,0,1+n'] * ||value[b,h,1+n',:]||
// 8 rows/warp, 4 lanes/row (4x float4 each) — the variant ncu measured at
// 12.5us. One red.add per warp for the denominator (exact *0.25 scale).
// Grid: 128 x 256.
// ---------------------------------------------------------------------------
__global__ void cls_kernel(const float* __restrict__ attn,
                           const float* __restrict__ value) {
    int warpid = threadIdx.x >> 5;
    int lane   = threadIdx.x & 31;
    int gw = blockIdx.x * 8 + warpid;       // 0..1023
    int b  = gw >> 7;
    int w  = gw & 127;

    int q = lane >> 2;                      // row within warp (0..7)
    int c = lane & 3;                       // chunk within row (0..3)
    int np = w * 8 + q;
    bool valid = (np < NM1);
    int row = valid ? (np + 1) : 1;

    float acc = 0.0f;
#pragma unroll
    for (int h = 0; h < H; ++h) {
        const float4* v4 = (const float4*)(value + (((size_t)(b * H + h)) * N + row) * D);
        float s = 0.0f;
#pragma unroll
        for (int kk = 0; kk < 4; ++kk) {
            float4 t = v4[c + 4 * kk];
            s += t.x * t.x + t.y * t.y + t.z * t.z + t.w * t.w;
        }
        s += __shfl_xor_sync(0xFFFFFFFFu, s, 1);
        s += __shfl_xor_sync(0xFFFFFFFFu, s, 2);
        float a = attn[((size_t)(b * H + h)) * ((size_t)N * N) + (size_t)row];
        acc += sqrtf(s) * a;
    }
    if (!valid) acc = 0.0f;
    if (valid && c == 0) g_cls[b * N + np] = acc;

    float t = acc;
#pragma unroll
    for (int o = 16; o > 0; o >>= 1) t += __shfl_xor_sync(0xFFFFFFFFu, t, o);
    if (lane == 0) atomicAdd(&g_denom[b], t * 0.25f);
}

// ---------------------------------------------------------------------------
// Kernel 2 (PDL secondary): ratio-space Gumbel argmax + per-batch dedup.
// Phase 1 (independent of cls): load gumbel_u, compute l = -log(u+eps)+eps.
// Then cudaGridDependencySynchronize(), read g_cls/g_denom, combine, reduce.
//   argmax_n( pl+g ) == argmax_n( c[n]/l[n] ),  c = cls/denom + eps, both > 0;
//   compare via c*bl > bc*l (no division).
// ---------------------------------------------------------------------------
__global__ void argmax_dedup_kernel(const float* __restrict__ gumbel_u,
                                    float* __restrict__ out, int write_extra,
                                    size_t off_mask, size_t off_ids) {
    int bj  = blockIdx.x;            // 0 .. B*K-1
    int b   = bj / K;
    int tid = threadIdx.x;           // 128

    const float* gu = gumbel_u + (size_t)bj * NM1;

    // ---- phase 1: gumbel transform (independent of predecessor) ----
    float lv[8];
#pragma unroll
    for (int i = 0; i < 8; ++i) {
        int n = tid + i * 128;
        float u = (n < NM1) ? gu[n] : 0.5f;
        lv[i] = -logf(u + EPSF) + EPSF;
    }

    // ---- wait for cls results ----
    cudaGridDependencySynchronize();

    const float* cls = g_cls + b * N;
    float invd = 1.0f / (g_denom[b] + EPSF);

    float bc = 0.0f, bl = 1.0f;
    int bidx = 0x7FFFFFFF;
#pragma unroll
    for (int i = 0; i < 8; ++i) {
        int n = tid + i * 128;
        if (n < NM1) {
            float l = lv[i];
            float c = fmaf(cls[n], invd, EPSF);
            float lhs = c * bl, rhs = bc * l;
            if (lhs > rhs || (lhs == rhs && n < bidx)) { bc = c; bl = l; bidx = n; }
        }
    }

    __shared__ float svc[128];
    __shared__ float svl[128];
    __shared__ int   si[128];
    svc[tid] = bc; svl[tid] = bl; si[tid] = bidx;
    __syncthreads();
#pragma unroll
    for (int s = 64; s > 0; s >>= 1) {
        if (tid < s) {
            float c2 = svc[tid + s], l2 = svl[tid + s]; int i2 = si[tid + s];
            float lhs = c2 * svl[tid], rhs = svc[tid] * l2;
            if (lhs > rhs || (lhs == rhs && i2 < si[tid])) {
                svc[tid] = c2; svl[tid] = l2; si[tid] = i2;
            }
        }
        __syncthreads();
    }
    if (tid == 0) g_sampled[bj] = si[0] + 1;

    // ---- last-block-per-batch dedup ----
    __threadfence();
    __shared__ int lastflag;
    if (tid == 0) lastflag = (atomicAdd(&g_cnt[b], 1) == K - 1);
    __syncthreads();
    if (!lastflag) return;
    if (tid == 0) { g_cnt[b] = 0; g_denom[b] = 0.0f; }   // self-reset
    __threadfence();

    __shared__ unsigned int bits[32];
    if (tid < 32) {
        int lane = tid;
        bits[lane] = 0u;
        __syncwarp();
        for (int i = lane; i < K; i += 32) {
            int s = g_sampled[b * K + i];      // 1..1023
            atomicOr(&bits[s >> 5], 1u << (s & 31));
        }
        __syncwarp();

        unsigned int myword = bits[lane];
        int cnt = __popc(myword);
        int incl = cnt;
#pragma unroll
        for (int o = 1; o < 32; o <<= 1) {
            int t = __shfl_up_sync(0xFFFFFFFFu, incl, o);
            if (lane >= o) incl += t;
        }
        int U = __shfl_sync(0xFFFFFFFFu, incl, 31);
        int excl = incl - cnt;
        int zeros = KP1 - U;

        for (int t = lane; t < zeros; t += 32) g_ids[b * KP1 + t] = 0;

        int pos = zeros + excl;
        unsigned int m = myword;
        while (m) {
            int p = __ffs(m) - 1;
            m &= m - 1;
            g_ids[b * KP1 + pos] = lane * 32 + p;
            pos++;
        }
        __syncwarp();

        if (write_extra) {
            for (int t = lane; t < KP1; t += 32) {
                int idv = g_ids[b * KP1 + t];
                out[off_mask + (size_t)b * KP1 + t] = (t == 0 || idv != 0) ? 1.0f : 0.0f;
                out[off_ids  + (size_t)b * KP1 + t] = (float)idv;
            }
        }
    }
}

// ---------------------------------------------------------------------------
// Kernel 3 (PDL secondary): row gather, 12-way ILP. Block = one (b, j).
// Grid-dep-sync first (g_ids comes from predecessor), then load 12 independent
// float4s into registers, store 12 (streaming).
// ---------------------------------------------------------------------------
__global__ void gather_kernel(const float* __restrict__ attn,
                              float* __restrict__ out) {
    cudaGridDependencySynchronize();

    int j = blockIdx.x;                  // 0..256
    int b = blockIdx.y;                  // 0..7
    int t = threadIdx.x;                 // 0..255
    int id = g_ids[b * KP1 + j];

    float4 v[H];
#pragma unroll
    for (int h = 0; h < H; ++h) {
        const float4* src = (const float4*)(attn + (((size_t)(b * H + h)) * N + id) * N);
        v[h] = __ldg(src + t);
    }
#pragma unroll
    for (int h = 0; h < H; ++h) {
        float4* dst = (float4*)(out + (((size_t)(b * H + h)) * KP1 + j) * N);
        __stcs(dst + t, v[h]);
    }
}

// ---------------------------------------------------------------------------
extern "C" void kernel_launch(void* const* d_in, const int* in_sizes, int n_in,
                              void* d_out, int out_size) {
    const float* attn     = (const float*)d_in[0];
    const float* value    = (const float*)d_in[1];
    const float* gumbel_u = (const float*)d_in[3];
    float* out = (float*)d_out;

    const size_t ATTN_OUT = (size_t)B * H * KP1 * N;     // 25,276,416
    const size_t MASK_OUT = (size_t)B * KP1;             // 2,056
    const size_t TOTAL    = ATTN_OUT + 2 * MASK_OUT;
    int write_extra = ((size_t)out_size >= TOTAL) ? 1 : 0;

    cls_kernel<<<128, 256>>>(attn, value);

    // argmax: PDL overlap with cls (phase 1 independent)
    {
        cudaLaunchConfig_t cfg = {};
        cfg.gridDim  = dim3(B * K, 1, 1);
        cfg.blockDim = dim3(128, 1, 1);
        cfg.stream   = 0;
        cudaLaunchAttribute at[1];
        at[0].id = cudaLaunchAttributeProgrammaticStreamSerialization;
        at[0].val.programmaticStreamSerializationAllowed = 1;
        cfg.attrs = at; cfg.numAttrs = 1;
        cudaLaunchKernelEx(&cfg, argmax_dedup_kernel, gumbel_u, out, write_extra,
                           ATTN_OUT, ATTN_OUT + MASK_OUT);
    }

    // gather: PDL to shave the launch gap (syncs before reading ids)
    {
        cudaLaunchConfig_t cfg = {};
        cfg.gridDim  = dim3(KP1, B, 1);
        cfg.blockDim = dim3(256, 1, 1);
        cfg.stream   = 0;
        cudaLaunchAttribute at[1];
        at[0].id = cudaLaunchAttributeProgrammaticStreamSerialization;
        at[0].val.programmaticStreamSerializationAllowed = 1;
        cfg.attrs = at; cfg.numAttrs = 1;
        cudaLaunchKernelEx(&cfg, gather_kernel, attn, out);
    }
}